// round 3
// baseline (speedup 1.0000x reference)
#include <cuda_runtime.h>
#include <math.h>
#include <stdint.h>

#define Bsz   8192
#define Ddim  512
#define Kneg  2048
#define NPAD  4096
#define EPSN  1e-8f

// ================= scratch =================
__device__ float g_C[(size_t)Bsz * NPAD];
__device__ float g_Ahi[(size_t)Bsz * Ddim];
__device__ float g_Alo[(size_t)Bsz * Ddim];
__device__ float g_Bhi[(size_t)NPAD * Ddim];
__device__ float g_Blo[(size_t)NPAD * Ddim];
__device__ float g_ni[Bsz], g_nj[Bsz], g_plog[Bsz];
__device__ int   g_mark[Bsz], g_slot[Bsz];
__device__ int   g_Ulist[NPAD];
__device__ int   g_map0[Kneg], g_map1[Kneg];
__device__ float g_nj0[Kneg], g_nj1[Kneg];
__device__ int   g_Ucnt;
__device__ float g_loss[Bsz];
__device__ int   g_cnt[Bsz];

// ================= small PTX helpers (all plain-sm_103 safe) =================
__device__ __forceinline__ uint32_t smem_u32(const void* p) {
    uint32_t a;
    asm("{ .reg .u64 t; cvta.to.shared.u64 t, %1; cvt.u32.u64 %0, t; }" : "=r"(a) : "l"(p));
    return a;
}
__device__ __forceinline__ float tf32_rna(float x) {
    uint32_t r;
    asm("cvt.rna.tf32.f32 %0, %1;" : "=r"(r) : "f"(x));
    return __uint_as_float(r);
}
__device__ __forceinline__ void cp16(uint32_t dst, const float* src) {
    asm volatile("cp.async.cg.shared.global [%0], [%1], 16;" :: "r"(dst), "l"(src));
}
__device__ __forceinline__ void cp_commit() { asm volatile("cp.async.commit_group;"); }
__device__ __forceinline__ void cp_wait1()  { asm volatile("cp.async.wait_group 1;" ::: "memory"); }
__device__ __forceinline__ void cp_wait0()  { asm volatile("cp.async.wait_group 0;" ::: "memory"); }
__device__ __forceinline__ void ldsv2(uint32_t addr, uint32_t& x, uint32_t& y) {
    asm volatile("ld.shared.v2.b32 {%0,%1}, [%2];" : "=r"(x), "=r"(y) : "r"(addr));
}
__device__ __forceinline__ void mma8(float d[4], const uint32_t a[4], const uint32_t b[2]) {
    asm volatile(
        "mma.sync.aligned.m16n8k8.row.col.f32.tf32.tf32.f32 "
        "{%0,%1,%2,%3}, {%4,%5,%6,%7}, {%8,%9}, {%0,%1,%2,%3};"
        : "+f"(d[0]), "+f"(d[1]), "+f"(d[2]), "+f"(d[3])
        : "r"(a[0]), "r"(a[1]), "r"(a[2]), "r"(a[3]), "r"(b[0]), "r"(b[1]));
}

// ================= setup kernels =================
__global__ void zero_mark_kernel() {
    int i = blockIdx.x * blockDim.x + threadIdx.x;
    if (i < Bsz) g_mark[i] = 0;
}

__global__ void norms_kernel(const float* __restrict__ zi, const float* __restrict__ zj) {
    int warp = (blockIdx.x * blockDim.x + threadIdx.x) >> 5;
    int lane = threadIdx.x & 31;
    if (warp >= Bsz) return;
    const float4* a = (const float4*)(zi + (size_t)warp * Ddim);
    const float4* b = (const float4*)(zj + (size_t)warp * Ddim);
    float si = 0.f, sj = 0.f, dij = 0.f;
#pragma unroll
    for (int c = 0; c < 4; c++) {
        float4 x = a[c * 32 + lane];
        float4 y = b[c * 32 + lane];
        si  += x.x*x.x + x.y*x.y + x.z*x.z + x.w*x.w;
        sj  += y.x*y.x + y.y*y.y + y.z*y.z + y.w*y.w;
        dij += x.x*y.x + x.y*y.y + x.z*y.z + x.w*y.w;
    }
#pragma unroll
    for (int o = 16; o > 0; o >>= 1) {
        si  += __shfl_down_sync(0xffffffffu, si, o);
        sj  += __shfl_down_sync(0xffffffffu, sj, o);
        dij += __shfl_down_sync(0xffffffffu, dij, o);
    }
    if (lane == 0) {
        float ni = sqrtf(si), nj = sqrtf(sj);
        g_ni[warp] = ni;
        g_nj[warp] = nj;
        g_plog[warp] = dij / fmaxf(ni * nj, EPSN) * 2.0f;
    }
}

__global__ void scatter_kernel(const int* __restrict__ perm) {
    int k = blockIdx.x * blockDim.x + threadIdx.x;
    if (k < Kneg) {
        int p = perm[k];
        g_mark[p] = 1;
        g_mark[p + 1] = 1;
    }
}

__global__ void scan_kernel() {
    __shared__ int ssum[1024];
    int tid = threadIdx.x;
    int base = tid * 8;
    int v[8], pre[8];
    int s = 0;
#pragma unroll
    for (int j = 0; j < 8; j++) {
        v[j] = g_mark[base + j];
        pre[j] = s;
        s += v[j];
    }
    ssum[tid] = s;
    __syncthreads();
    for (int off = 1; off < 1024; off <<= 1) {
        int t = (tid >= off) ? ssum[tid - off] : 0;
        __syncthreads();
        ssum[tid] += t;
        __syncthreads();
    }
    int excl = ssum[tid] - s;
#pragma unroll
    for (int j = 0; j < 8; j++) g_slot[base + j] = excl + pre[j];
    if (tid == 1023) g_Ucnt = ssum[1023];
}

__global__ void build_kernel() {
    int j = blockIdx.x * blockDim.x + threadIdx.x;
    if (j < Bsz && g_mark[j]) g_Ulist[g_slot[j]] = j;
    if (j < NPAD && j >= g_Ucnt) g_Ulist[j] = 0;
}

__global__ void maps_kernel(const int* __restrict__ perm) {
    int k = blockIdx.x * blockDim.x + threadIdx.x;
    if (k < Kneg) {
        int p = perm[k];
        g_map0[k] = g_slot[p];
        g_map1[k] = g_slot[p + 1];
        g_nj0[k] = g_nj[p];
        g_nj1[k] = g_nj[p + 1];
    }
}

// ================= split pre-pass =================
// Writes hi/lo in k-interleaved order: within each k8 group, slot layout is
// [c0,c4,c1,c5,c2,c6,c3,c7] so fragment pairs (p, p+4) are adjacent.
__device__ __forceinline__ void split_row_group(const float* __restrict__ src,
                                                float* __restrict__ hi_out,
                                                float* __restrict__ lo_out) {
    float4 a = *(const float4*)(src);       // k .. k+3
    float4 b = *(const float4*)(src + 4);   // k+4 .. k+7
    float4 ah = make_float4(tf32_rna(a.x), tf32_rna(a.y), tf32_rna(a.z), tf32_rna(a.w));
    float4 bh = make_float4(tf32_rna(b.x), tf32_rna(b.y), tf32_rna(b.z), tf32_rna(b.w));
    float4 al = make_float4(tf32_rna(a.x - ah.x), tf32_rna(a.y - ah.y),
                            tf32_rna(a.z - ah.z), tf32_rna(a.w - ah.w));
    float4 bl = make_float4(tf32_rna(b.x - bh.x), tf32_rna(b.y - bh.y),
                            tf32_rna(b.z - bh.z), tf32_rna(b.w - bh.w));
    *(float4*)(hi_out)     = make_float4(ah.x, bh.x, ah.y, bh.y);
    *(float4*)(hi_out + 4) = make_float4(ah.z, bh.z, ah.w, bh.w);
    *(float4*)(lo_out)     = make_float4(al.x, bl.x, al.y, bl.y);
    *(float4*)(lo_out + 4) = make_float4(al.z, bl.z, al.w, bl.w);
}

__global__ void split_zi_kernel(const float* __restrict__ zi) {
    int idx = blockIdx.x * blockDim.x + threadIdx.x;   // Bsz*64
    int row = idx >> 6;
    int g   = idx & 63;
    size_t off = (size_t)row * Ddim + g * 8;
    split_row_group(zi + off, g_Ahi + off, g_Alo + off);
}

__global__ void split_zj_kernel(const float* __restrict__ zj) {
    int idx = blockIdx.x * blockDim.x + threadIdx.x;   // NPAD*64
    int u = idx >> 6;
    int g = idx & 63;
    int row = g_Ulist[u];
    size_t doff = (size_t)u * Ddim + g * 8;
    size_t soff = (size_t)row * Ddim + g * 8;
    split_row_group(zj + soff, g_Bhi + doff, g_Blo + doff);
}

// ================= 3. GEMM: mma.sync tf32, 3xTF32 =================
// Block 128x128, 256 threads (8 warps), warp tile 32x64.
// K chunks of 32 floats, 2-stage cp.async double buffer.
#define SSTR    36                    // floats per smem row (144B, 16B aligned)
#define ARR_F   (128 * SSTR)          // 4608 floats per array
#define ARR_B   (ARR_F * 4)           // 18432 bytes
#define STAGE_F (4 * ARR_F)           // 18432 floats
#define STAGE_B (STAGE_F * 4)         // 73728 bytes
#define SMEM_TOTAL (2 * STAGE_B)      // 147456 bytes
#define NCHUNK  (Ddim / 32)           // 16

__global__ __launch_bounds__(256, 1) void gemm_mma_kernel() {
    const int n0 = blockIdx.x * 128;
    const int m0 = blockIdx.y * 128;
    if (n0 >= g_Ucnt) return;

    extern __shared__ float sm[];
    const uint32_t sb = smem_u32(sm);

    const int tid  = threadIdx.x;
    const int lane = tid & 31;
    const int wid  = tid >> 5;
    const int wm   = wid >> 1;        // 0..3  (32-row slices)
    const int wn   = wid & 1;         // 0..1  (64-col slices)

    // cp.async source/dest for this thread: row = tid>>1, half = tid&1
    const int lrow = tid >> 1;
    const int lhalf = tid & 1;
    const float* gsrc[4];
    gsrc[0] = g_Ahi + (size_t)(m0 + lrow) * Ddim + lhalf * 16;
    gsrc[1] = g_Alo + (size_t)(m0 + lrow) * Ddim + lhalf * 16;
    gsrc[2] = g_Bhi + (size_t)(n0 + lrow) * Ddim + lhalf * 16;
    gsrc[3] = g_Blo + (size_t)(n0 + lrow) * Ddim + lhalf * 16;
    const uint32_t sdst_base = sb + (uint32_t)(lrow * SSTR + lhalf * 16) * 4;

    // fragment LDS base addresses
    const uint32_t aoff = (uint32_t)(((wm * 32 + (lane >> 2)) * SSTR + (lane & 3) * 2) * 4);
    const uint32_t boff = (uint32_t)(((wn * 64 + (lane >> 2)) * SSTR + (lane & 3) * 2) * 4);

    float d[2][8][4];
#pragma unroll
    for (int mt = 0; mt < 2; mt++)
#pragma unroll
        for (int nt = 0; nt < 8; nt++)
#pragma unroll
            for (int q = 0; q < 4; q++) d[mt][nt][q] = 0.f;

    // ---- prologue: prefetch chunk 0 into stage 0 ----
    {
        const uint32_t st0 = sdst_base;
#pragma unroll
        for (int arr = 0; arr < 4; arr++) {
            const float* s = gsrc[arr];
            uint32_t dsta = st0 + arr * ARR_B;
#pragma unroll
            for (int q = 0; q < 4; q++) cp16(dsta + q * 16, s + q * 4);
        }
        cp_commit();
    }

    for (int c = 0; c < NCHUNK; c++) {
        const int stc = c & 1;
        if (c + 1 < NCHUNK) {
            const uint32_t stn = sdst_base + ((c + 1) & 1) * STAGE_B;
#pragma unroll
            for (int arr = 0; arr < 4; arr++) {
                const float* s = gsrc[arr] + (c + 1) * 32;
                uint32_t dsta = stn + arr * ARR_B;
#pragma unroll
                for (int q = 0; q < 4; q++) cp16(dsta + q * 16, s + q * 4);
            }
            cp_commit();
            cp_wait1();
        } else {
            cp_wait0();
        }
        __syncthreads();

        const uint32_t s0 = sb + stc * STAGE_B;
#pragma unroll
        for (int g = 0; g < 4; g++) {
            const uint32_t go = g * 32;   // bytes: g*8 floats
            uint32_t ah[2][4], al[2][4], bh[8][2], bl[8][2];
#pragma unroll
            for (int mt = 0; mt < 2; mt++) {
                uint32_t base = s0 + aoff + mt * (16 * SSTR * 4) + go;
                ldsv2(base,                 ah[mt][0], ah[mt][2]);
                ldsv2(base + 8 * SSTR * 4,  ah[mt][1], ah[mt][3]);
                uint32_t basl = base + ARR_B;
                ldsv2(basl,                 al[mt][0], al[mt][2]);
                ldsv2(basl + 8 * SSTR * 4,  al[mt][1], al[mt][3]);
            }
#pragma unroll
            for (int nt = 0; nt < 8; nt++) {
                uint32_t base = s0 + 2 * ARR_B + boff + nt * (8 * SSTR * 4) + go;
                ldsv2(base,         bh[nt][0], bh[nt][1]);
                ldsv2(base + ARR_B, bl[nt][0], bl[nt][1]);
            }
#pragma unroll
            for (int mt = 0; mt < 2; mt++)
#pragma unroll
                for (int nt = 0; nt < 8; nt++) {
                    mma8(d[mt][nt], ah[mt], bh[nt]);
                    mma8(d[mt][nt], ah[mt], bl[nt]);
                    mma8(d[mt][nt], al[mt], bh[nt]);
                }
        }
        __syncthreads();
    }

    // ---- epilogue: store C frags ----
#pragma unroll
    for (int mt = 0; mt < 2; mt++) {
        int r0 = m0 + wm * 32 + mt * 16 + (lane >> 2);
#pragma unroll
        for (int nt = 0; nt < 8; nt++) {
            int col = n0 + wn * 64 + nt * 8 + (lane & 3) * 2;
            float* p0 = g_C + (size_t)r0 * NPAD + col;
            float* p1 = g_C + (size_t)(r0 + 8) * NPAD + col;
            *(float2*)p0 = make_float2(d[mt][nt][0], d[mt][nt][1]);
            *(float2*)p1 = make_float2(d[mt][nt][2], d[mt][nt][3]);
        }
    }
}

// ================= 4. per-row logsumexp + rank counts =================
__global__ __launch_bounds__(256) void reduce_kernel(const int* __restrict__ perm) {
    __shared__ int   s_p[Kneg];
    __shared__ int   s_m0[Kneg];
    __shared__ int   s_m1[Kneg];
    __shared__ float s_n0[Kneg];
    __shared__ float s_n1[Kneg];
    __shared__ float redf[256];
    __shared__ int   redi[256];

    int tid = threadIdx.x;
    for (int k = tid; k < Kneg; k += 256) {
        s_p[k]  = perm[k];
        s_m0[k] = g_map0[k];
        s_m1[k] = g_map1[k];
        s_n0[k] = g_nj0[k];
        s_n1[k] = g_nj1[k];
    }
    __syncthreads();

    for (int r = 0; r < 8; r++) {
        int i = blockIdx.x * 8 + r;
        float ni = g_ni[i];
        float lp = g_plog[i];
        const float* Crow = g_C + (size_t)i * NPAD;

        float tmax = lp;
        for (int k = tid; k < Kneg; k += 256) {
            bool sel = (s_p[k] >= i);
            int slot  = sel ? s_m1[k] : s_m0[k];
            float njc = sel ? s_n1[k] : s_n0[k];
            float l = Crow[slot] / fmaxf(ni * njc, EPSN) * 2.0f;
            tmax = fmaxf(tmax, l);
        }
        redf[tid] = tmax;
        __syncthreads();
        for (int o = 128; o > 0; o >>= 1) {
            if (tid < o) redf[tid] = fmaxf(redf[tid], redf[tid + o]);
            __syncthreads();
        }
        float M = redf[0];
        __syncthreads();

        float s = 0.f;
        int cnt = 0;
        for (int k = tid; k < Kneg; k += 256) {
            bool sel = (s_p[k] >= i);
            int slot  = sel ? s_m1[k] : s_m0[k];
            float njc = sel ? s_n1[k] : s_n0[k];
            float l = Crow[slot] / fmaxf(ni * njc, EPSN) * 2.0f;
            s += expf(l - M);
            cnt += (l > lp) ? 1 : 0;
        }
        redf[tid] = s;
        redi[tid] = cnt;
        __syncthreads();
        for (int o = 128; o > 0; o >>= 1) {
            if (tid < o) { redf[tid] += redf[tid + o]; redi[tid] += redi[tid + o]; }
            __syncthreads();
        }
        if (tid == 0) {
            g_loss[i] = M + logf(redf[0] + expf(lp - M)) - lp;
            g_cnt[i]  = redi[0];
        }
        __syncthreads();
    }
}

// ================= 5. final reduction =================
__global__ void final_kernel(float* __restrict__ out) {
    __shared__ float sf[1024];
    __shared__ int   s1[1024];
    __shared__ int   s5[1024];
    int tid = threadIdx.x;
    float s = 0.f;
    int c1 = 0, c5 = 0;
    for (int i = tid; i < Bsz; i += 1024) {
        s += g_loss[i];
        int c = g_cnt[i];
        c1 += (c == 0) ? 1 : 0;
        c5 += (c <= 4) ? 1 : 0;
    }
    sf[tid] = s; s1[tid] = c1; s5[tid] = c5;
    __syncthreads();
    for (int o = 512; o > 0; o >>= 1) {
        if (tid < o) { sf[tid] += sf[tid + o]; s1[tid] += s1[tid + o]; s5[tid] += s5[tid + o]; }
        __syncthreads();
    }
    if (tid == 0) {
        out[0] = sf[0] / (float)Bsz;
        out[1] = 100.0f * (float)s1[0] / (float)Bsz;
        out[2] = 100.0f * (float)s5[0] / (float)Bsz;
    }
}

// ================= launch =================
extern "C" void kernel_launch(void* const* d_in, const int* in_sizes, int n_in,
                              void* d_out, int out_size) {
    const float* zi   = (const float*)d_in[0];
    const float* zj   = (const float*)d_in[1];
    const int*   perm = (const int*)d_in[2];
    float* out = (float*)d_out;

    cudaFuncSetAttribute(gemm_mma_kernel, cudaFuncAttributeMaxDynamicSharedMemorySize, SMEM_TOTAL);

    zero_mark_kernel<<<8, 1024>>>();
    norms_kernel<<<Bsz / 8, 256>>>(zi, zj);
    scatter_kernel<<<2, 1024>>>(perm);
    scan_kernel<<<1, 1024>>>();
    build_kernel<<<8, 1024>>>();
    maps_kernel<<<2, 1024>>>(perm);

    split_zi_kernel<<<Bsz * 64 / 256, 256>>>(zi);
    split_zj_kernel<<<NPAD * 64 / 256, 256>>>(zj);

    dim3 g(NPAD / 128, Bsz / 128);     // 32 x 64
    gemm_mma_kernel<<<g, 256, SMEM_TOTAL>>>();

    reduce_kernel<<<Bsz / 8, 256>>>(perm);
    final_kernel<<<1, 1024>>>(out);
}

// round 5
// speedup vs baseline: 1.6979x; 1.6979x over previous
#include <cuda_runtime.h>
#include <cuda_bf16.h>
#include <math.h>
#include <stdint.h>

#define Bsz   8192
#define Ddim  512
#define Kneg  2048
#define NPAD  4096
#define EPSN  1e-8f

// ================= scratch =================
__device__ float        g_C[(size_t)Bsz * NPAD];
__device__ __nv_bfloat16 g_Ahi[(size_t)Bsz * Ddim];
__device__ __nv_bfloat16 g_Alo[(size_t)Bsz * Ddim];
__device__ __nv_bfloat16 g_Bhi[(size_t)NPAD * Ddim];
__device__ __nv_bfloat16 g_Blo[(size_t)NPAD * Ddim];
__device__ float g_ni[Bsz], g_nj[Bsz], g_plog[Bsz];
__device__ int   g_mark[Bsz], g_slot[Bsz];
__device__ int   g_Ulist[NPAD];
__device__ int   g_map0[Kneg], g_map1[Kneg];
__device__ float g_nj0[Kneg], g_nj1[Kneg];
__device__ int   g_Ucnt;
__device__ float g_loss[Bsz];
__device__ int   g_cnt[Bsz];

// ================= PTX helpers (plain sm_103-safe) =================
__device__ __forceinline__ uint32_t smem_u32(const void* p) {
    uint32_t a;
    asm("{ .reg .u64 t; cvta.to.shared.u64 t, %1; cvt.u32.u64 %0, t; }" : "=r"(a) : "l"(p));
    return a;
}
__device__ __forceinline__ void cp16(uint32_t dst, const void* src) {
    asm volatile("cp.async.cg.shared.global [%0], [%1], 16;" :: "r"(dst), "l"(src));
}
__device__ __forceinline__ void cp_commit() { asm volatile("cp.async.commit_group;"); }
__device__ __forceinline__ void cp_wait1()  { asm volatile("cp.async.wait_group 1;" ::: "memory"); }
__device__ __forceinline__ void cp_wait0()  { asm volatile("cp.async.wait_group 0;" ::: "memory"); }
__device__ __forceinline__ void ldsm_x4(uint32_t addr, uint32_t& r0, uint32_t& r1,
                                        uint32_t& r2, uint32_t& r3) {
    asm volatile("ldmatrix.sync.aligned.m8n8.x4.shared.b16 {%0,%1,%2,%3}, [%4];"
                 : "=r"(r0), "=r"(r1), "=r"(r2), "=r"(r3) : "r"(addr));
}
__device__ __forceinline__ void mma_bf16(float d[4], const uint32_t a[4], const uint32_t b[2]) {
    asm volatile(
        "mma.sync.aligned.m16n8k16.row.col.f32.bf16.bf16.f32 "
        "{%0,%1,%2,%3}, {%4,%5,%6,%7}, {%8,%9}, {%0,%1,%2,%3};"
        : "+f"(d[0]), "+f"(d[1]), "+f"(d[2]), "+f"(d[3])
        : "r"(a[0]), "r"(a[1]), "r"(a[2]), "r"(a[3]), "r"(b[0]), "r"(b[1]));
}

// ================= setup kernels =================
__global__ void zero_mark_kernel() {
    int i = blockIdx.x * blockDim.x + threadIdx.x;
    if (i < Bsz) g_mark[i] = 0;
}

__global__ void norms_kernel(const float* __restrict__ zi, const float* __restrict__ zj) {
    int warp = (blockIdx.x * blockDim.x + threadIdx.x) >> 5;
    int lane = threadIdx.x & 31;
    if (warp >= Bsz) return;
    const float4* a = (const float4*)(zi + (size_t)warp * Ddim);
    const float4* b = (const float4*)(zj + (size_t)warp * Ddim);
    float si = 0.f, sj = 0.f, dij = 0.f;
#pragma unroll
    for (int c = 0; c < 4; c++) {
        float4 x = a[c * 32 + lane];
        float4 y = b[c * 32 + lane];
        si  += x.x*x.x + x.y*x.y + x.z*x.z + x.w*x.w;
        sj  += y.x*y.x + y.y*y.y + y.z*y.z + y.w*y.w;
        dij += x.x*y.x + x.y*y.y + x.z*y.z + x.w*y.w;
    }
#pragma unroll
    for (int o = 16; o > 0; o >>= 1) {
        si  += __shfl_down_sync(0xffffffffu, si, o);
        sj  += __shfl_down_sync(0xffffffffu, sj, o);
        dij += __shfl_down_sync(0xffffffffu, dij, o);
    }
    if (lane == 0) {
        float ni = sqrtf(si), nj = sqrtf(sj);
        g_ni[warp] = ni;
        g_nj[warp] = nj;
        g_plog[warp] = dij / fmaxf(ni * nj, EPSN) * 2.0f;
    }
}

__global__ void scatter_kernel(const int* __restrict__ perm) {
    int k = blockIdx.x * blockDim.x + threadIdx.x;
    if (k < Kneg) {
        int p = perm[k];
        g_mark[p] = 1;
        g_mark[p + 1] = 1;
    }
}

__global__ void scan_kernel() {
    __shared__ int ssum[1024];
    int tid = threadIdx.x;
    int base = tid * 8;
    int v[8], pre[8];
    int s = 0;
#pragma unroll
    for (int j = 0; j < 8; j++) {
        v[j] = g_mark[base + j];
        pre[j] = s;
        s += v[j];
    }
    ssum[tid] = s;
    __syncthreads();
    for (int off = 1; off < 1024; off <<= 1) {
        int t = (tid >= off) ? ssum[tid - off] : 0;
        __syncthreads();
        ssum[tid] += t;
        __syncthreads();
    }
    int excl = ssum[tid] - s;
#pragma unroll
    for (int j = 0; j < 8; j++) g_slot[base + j] = excl + pre[j];
    if (tid == 1023) g_Ucnt = ssum[1023];
}

__global__ void build_kernel() {
    int j = blockIdx.x * blockDim.x + threadIdx.x;
    if (j < Bsz && g_mark[j]) g_Ulist[g_slot[j]] = j;
    if (j < NPAD && j >= g_Ucnt) g_Ulist[j] = 0;
}

__global__ void maps_kernel(const int* __restrict__ perm) {
    int k = blockIdx.x * blockDim.x + threadIdx.x;
    if (k < Kneg) {
        int p = perm[k];
        g_map0[k] = g_slot[p];
        g_map1[k] = g_slot[p + 1];
        g_nj0[k] = g_nj[p];
        g_nj1[k] = g_nj[p + 1];
    }
}

// ================= bf16 hi/lo split pre-pass (plain [row][k] layout) =================
__device__ __forceinline__ void split8(const float* __restrict__ src,
                                       __nv_bfloat16* __restrict__ hi_out,
                                       __nv_bfloat16* __restrict__ lo_out) {
    float4 a = *(const float4*)(src);
    float4 b = *(const float4*)(src + 4);
    __nv_bfloat16 h[8], l[8];
    float v[8] = {a.x, a.y, a.z, a.w, b.x, b.y, b.z, b.w};
#pragma unroll
    for (int q = 0; q < 8; q++) {
        h[q] = __float2bfloat16(v[q]);
        l[q] = __float2bfloat16(v[q] - __bfloat162float(h[q]));
    }
    *(uint4*)hi_out = *(uint4*)h;
    *(uint4*)lo_out = *(uint4*)l;
}

__global__ void split_zi_kernel(const float* __restrict__ zi) {
    int idx = blockIdx.x * blockDim.x + threadIdx.x;   // Bsz*64
    size_t off = (size_t)idx * 8;
    split8(zi + off, g_Ahi + off, g_Alo + off);
}

__global__ void split_zj_kernel(const float* __restrict__ zj) {
    int idx = blockIdx.x * blockDim.x + threadIdx.x;   // NPAD*64
    int u = idx >> 6;
    int g = idx & 63;
    int row = g_Ulist[u];
    size_t doff = (size_t)u * Ddim + g * 8;
    size_t soff = (size_t)row * Ddim + g * 8;
    split8(zj + soff, g_Bhi + doff, g_Blo + doff);
}

// ================= 3. GEMM: mma.sync bf16 m16n8k16, 3-term split =================
// Block 128x128, 256 threads (8 warps), warp tile 32x64. K chunks of 32, 2-stage cp.async.
#define RSTRB   80                    // bytes per smem row (40 bf16, 16B-multiple)
#define ARRB    (128 * RSTRB)         // 10240 B per array
#define STGB    (4 * ARRB)            // 40960 B per stage
#define SMEM_TOTAL (2 * STGB)         // 81920 B
#define NCHUNK  (Ddim / 32)           // 16

__global__ __launch_bounds__(256, 2) void gemm_bf16_kernel() {
    const int n0 = blockIdx.x * 128;
    const int m0 = blockIdx.y * 128;
    if (n0 >= g_Ucnt) return;

    extern __shared__ char sm[];
    const uint32_t sb = smem_u32(sm);

    const int tid  = threadIdx.x;
    const int lane = tid & 31;
    const int wid  = tid >> 5;
    const int wm   = wid >> 1;        // 0..3
    const int wn   = wid & 1;         // 0..1

    // ---- cp.async assignment: arr = tid>>6, 8 x 16B per thread ----
    const int arr = tid >> 6;         // 0:Ahi 1:Alo 2:Bhi 3:Blo
    const int lt  = tid & 63;
    const __nv_bfloat16* garr =
        (arr == 0) ? g_Ahi + (size_t)m0 * Ddim :
        (arr == 1) ? g_Alo + (size_t)m0 * Ddim :
        (arr == 2) ? g_Bhi + (size_t)n0 * Ddim :
                     g_Blo + (size_t)n0 * Ddim;

    float d[2][8][4];
#pragma unroll
    for (int mt = 0; mt < 2; mt++)
#pragma unroll
        for (int nt = 0; nt < 8; nt++)
#pragma unroll
            for (int q = 0; q < 4; q++) d[mt][nt][q] = 0.f;

    // prologue: chunk 0 -> stage 0
#pragma unroll
    for (int q = 0; q < 8; q++) {
        int idx = lt * 8 + q;          // 0..511
        int row = idx >> 2;
        int c16 = idx & 3;
        cp16(sb + arr * ARRB + row * RSTRB + c16 * 16,
             garr + (size_t)row * Ddim + c16 * 8);
    }
    cp_commit();

    // ldmatrix lane-address components
    const int a_row_in = ((lane >> 3) & 1) * 8 + (lane & 7);   // row within m16
    const int a_kb     = (lane >> 4) * 16;                     // 0 or 16 bytes
    const int b_nrow_in = ((lane >> 4) << 3) + (lane & 7);     // row within n16 pair
    const int b_kb      = ((lane >> 3) & 1) * 16;

    for (int c = 0; c < NCHUNK; c++) {
        if (c + 1 < NCHUNK) {
            const uint32_t stn = sb + ((c + 1) & 1) * STGB;
            const __nv_bfloat16* gsrc = garr + (c + 1) * 32;
#pragma unroll
            for (int q = 0; q < 8; q++) {
                int idx = lt * 8 + q;
                int row = idx >> 2;
                int c16 = idx & 3;
                cp16(stn + arr * ARRB + row * RSTRB + c16 * 16,
                     gsrc + (size_t)row * Ddim + c16 * 8);
            }
            cp_commit();
            cp_wait1();
        } else {
            cp_wait0();
        }
        __syncthreads();

        const uint32_t s0 = sb + (c & 1) * STGB;
#pragma unroll
        for (int g = 0; g < 2; g++) {           // two k16 groups per chunk
            const int kb = g * 32;
            uint32_t ah[2][4], al[2][4];
#pragma unroll
            for (int mt = 0; mt < 2; mt++) {
                uint32_t ra = s0 + (wm * 32 + mt * 16 + a_row_in) * RSTRB + kb + a_kb;
                ldsm_x4(ra,        ah[mt][0], ah[mt][1], ah[mt][2], ah[mt][3]);
                ldsm_x4(ra + ARRB, al[mt][0], al[mt][1], al[mt][2], al[mt][3]);
            }
#pragma unroll
            for (int p = 0; p < 4; p++) {       // pairs of n8 tiles
                uint32_t bh[4], bl[4];
                uint32_t rb = s0 + 2 * ARRB + (wn * 64 + p * 16 + b_nrow_in) * RSTRB + kb + b_kb;
                ldsm_x4(rb,        bh[0], bh[1], bh[2], bh[3]);
                ldsm_x4(rb + ARRB, bl[0], bl[1], bl[2], bl[3]);
#pragma unroll
                for (int mt = 0; mt < 2; mt++) {
#pragma unroll
                    for (int j = 0; j < 2; j++) {
                        float* acc = d[mt][p * 2 + j];
                        mma_bf16(acc, ah[mt], bh + j * 2);
                        mma_bf16(acc, ah[mt], bl + j * 2);
                        mma_bf16(acc, al[mt], bh + j * 2);
                    }
                }
            }
        }
        __syncthreads();
    }

    // ---- epilogue ----
#pragma unroll
    for (int mt = 0; mt < 2; mt++) {
        int r0 = m0 + wm * 32 + mt * 16 + (lane >> 2);
#pragma unroll
        for (int nt = 0; nt < 8; nt++) {
            int col = n0 + wn * 64 + nt * 8 + (lane & 3) * 2;
            float* p0 = g_C + (size_t)r0 * NPAD + col;
            float* p1 = g_C + (size_t)(r0 + 8) * NPAD + col;
            *(float2*)p0 = make_float2(d[mt][nt][0], d[mt][nt][1]);
            *(float2*)p1 = make_float2(d[mt][nt][2], d[mt][nt][3]);
        }
    }
}

// ================= 4. per-row logsumexp + rank counts =================
__global__ __launch_bounds__(256) void reduce_kernel(const int* __restrict__ perm) {
    __shared__ int   s_p[Kneg];
    __shared__ int   s_m0[Kneg];
    __shared__ int   s_m1[Kneg];
    __shared__ float s_n0[Kneg];
    __shared__ float s_n1[Kneg];
    __shared__ float redf[256];
    __shared__ int   redi[256];

    int tid = threadIdx.x;
    for (int k = tid; k < Kneg; k += 256) {
        s_p[k]  = perm[k];
        s_m0[k] = g_map0[k];
        s_m1[k] = g_map1[k];
        s_n0[k] = g_nj0[k];
        s_n1[k] = g_nj1[k];
    }
    __syncthreads();

    for (int r = 0; r < 8; r++) {
        int i = blockIdx.x * 8 + r;
        float ni = g_ni[i];
        float lp = g_plog[i];
        const float* Crow = g_C + (size_t)i * NPAD;

        float tmax = lp;
        for (int k = tid; k < Kneg; k += 256) {
            bool sel = (s_p[k] >= i);
            int slot  = sel ? s_m1[k] : s_m0[k];
            float njc = sel ? s_n1[k] : s_n0[k];
            float l = Crow[slot] / fmaxf(ni * njc, EPSN) * 2.0f;
            tmax = fmaxf(tmax, l);
        }
        redf[tid] = tmax;
        __syncthreads();
        for (int o = 128; o > 0; o >>= 1) {
            if (tid < o) redf[tid] = fmaxf(redf[tid], redf[tid + o]);
            __syncthreads();
        }
        float M = redf[0];
        __syncthreads();

        float s = 0.f;
        int cnt = 0;
        for (int k = tid; k < Kneg; k += 256) {
            bool sel = (s_p[k] >= i);
            int slot  = sel ? s_m1[k] : s_m0[k];
            float njc = sel ? s_n1[k] : s_n0[k];
            float l = Crow[slot] / fmaxf(ni * njc, EPSN) * 2.0f;
            s += expf(l - M);
            cnt += (l > lp) ? 1 : 0;
        }
        redf[tid] = s;
        redi[tid] = cnt;
        __syncthreads();
        for (int o = 128; o > 0; o >>= 1) {
            if (tid < o) { redf[tid] += redf[tid + o]; redi[tid] += redi[tid + o]; }
            __syncthreads();
        }
        if (tid == 0) {
            g_loss[i] = M + logf(redf[0] + expf(lp - M)) - lp;
            g_cnt[i]  = redi[0];
        }
        __syncthreads();
    }
}

// ================= 5. final reduction =================
__global__ void final_kernel(float* __restrict__ out) {
    __shared__ float sf[1024];
    __shared__ int   s1[1024];
    __shared__ int   s5[1024];
    int tid = threadIdx.x;
    float s = 0.f;
    int c1 = 0, c5 = 0;
    for (int i = tid; i < Bsz; i += 1024) {
        s += g_loss[i];
        int c = g_cnt[i];
        c1 += (c == 0) ? 1 : 0;
        c5 += (c <= 4) ? 1 : 0;
    }
    sf[tid] = s; s1[tid] = c1; s5[tid] = c5;
    __syncthreads();
    for (int o = 512; o > 0; o >>= 1) {
        if (tid < o) { sf[tid] += sf[tid + o]; s1[tid] += s1[tid + o]; s5[tid] += s5[tid + o]; }
        __syncthreads();
    }
    if (tid == 0) {
        out[0] = sf[0] / (float)Bsz;
        out[1] = 100.0f * (float)s1[0] / (float)Bsz;
        out[2] = 100.0f * (float)s5[0] / (float)Bsz;
    }
}

// ================= launch =================
extern "C" void kernel_launch(void* const* d_in, const int* in_sizes, int n_in,
                              void* d_out, int out_size) {
    const float* zi   = (const float*)d_in[0];
    const float* zj   = (const float*)d_in[1];
    const int*   perm = (const int*)d_in[2];
    float* out = (float*)d_out;

    cudaFuncSetAttribute(gemm_bf16_kernel, cudaFuncAttributeMaxDynamicSharedMemorySize, SMEM_TOTAL);

    zero_mark_kernel<<<8, 1024>>>();
    norms_kernel<<<Bsz / 8, 256>>>(zi, zj);
    scatter_kernel<<<2, 1024>>>(perm);
    scan_kernel<<<1, 1024>>>();
    build_kernel<<<8, 1024>>>();
    maps_kernel<<<2, 1024>>>(perm);

    split_zi_kernel<<<Bsz * 64 / 256, 256>>>(zi);
    split_zj_kernel<<<NPAD * 64 / 256, 256>>>(zj);

    dim3 g(NPAD / 128, Bsz / 128);     // 32 x 64
    gemm_bf16_kernel<<<g, 256, SMEM_TOTAL>>>();

    reduce_kernel<<<Bsz / 8, 256>>>(perm);
    final_kernel<<<1, 1024>>>(out);
}

// round 8
// speedup vs baseline: 2.1710x; 1.2786x over previous
#include <cuda_runtime.h>
#include <cuda_bf16.h>
#include <math.h>
#include <stdint.h>

#define Bsz   8192
#define Ddim  512
#define Kneg  2048
#define NPAD  4096
#define EPSN  1e-8f

// ================= scratch =================
__device__ float        g_C[(size_t)Bsz * NPAD];
__device__ __nv_bfloat16 g_Ahi[(size_t)Bsz * Ddim];
__device__ __nv_bfloat16 g_Alo[(size_t)Bsz * Ddim];
__device__ __nv_bfloat16 g_Bhi[(size_t)NPAD * Ddim];
__device__ __nv_bfloat16 g_Blo[(size_t)NPAD * Ddim];
__device__ float g_ni[Bsz], g_nj[Bsz], g_plog[Bsz];
__device__ int   g_mark[Bsz], g_slot[Bsz];
__device__ int   g_Ulist[NPAD];           // zero-init; pad slots stay 0 forever
__device__ int   g_map0[Kneg], g_map1[Kneg];
__device__ float g_nj0[Kneg], g_nj1[Kneg];
__device__ int   g_Ucnt;                  // reset to 0 by final_kernel each replay
__device__ float g_loss[Bsz];
__device__ int   g_cnt[Bsz];

// ================= PTX helpers =================
__device__ __forceinline__ uint32_t smem_u32(const void* p) {
    uint32_t a;
    asm("{ .reg .u64 t; cvta.to.shared.u64 t, %1; cvt.u32.u64 %0, t; }" : "=r"(a) : "l"(p));
    return a;
}
__device__ __forceinline__ void cp16(uint32_t dst, const void* src) {
    asm volatile("cp.async.cg.shared.global [%0], [%1], 16;" :: "r"(dst), "l"(src));
}
__device__ __forceinline__ void cp_commit() { asm volatile("cp.async.commit_group;"); }
__device__ __forceinline__ void cp_wait1()  { asm volatile("cp.async.wait_group 1;" ::: "memory"); }
__device__ __forceinline__ void cp_wait0()  { asm volatile("cp.async.wait_group 0;" ::: "memory"); }
__device__ __forceinline__ void ldsm_x4(uint32_t addr, uint32_t& r0, uint32_t& r1,
                                        uint32_t& r2, uint32_t& r3) {
    asm volatile("ldmatrix.sync.aligned.m8n8.x4.shared.b16 {%0,%1,%2,%3}, [%4];"
                 : "=r"(r0), "=r"(r1), "=r"(r2), "=r"(r3) : "r"(addr));
}
__device__ __forceinline__ void mma_bf16(float d[4], const uint32_t a[4], const uint32_t b[2]) {
    asm volatile(
        "mma.sync.aligned.m16n8k16.row.col.f32.bf16.bf16.f32 "
        "{%0,%1,%2,%3}, {%4,%5,%6,%7}, {%8,%9}, {%0,%1,%2,%3};"
        : "+f"(d[0]), "+f"(d[1]), "+f"(d[2]), "+f"(d[3])
        : "r"(a[0]), "r"(a[1]), "r"(a[2]), "r"(a[3]), "r"(b[0]), "r"(b[1]));
}

// ================= 0. assign: dedup marks + atomic slot assignment =================
// Slot order is nondeterministic, but every output bit is slot-independent:
// the GEMM value for column p doesn't depend on which slot p lands in, and the
// reduce kernel iterates in k-order through map0/map1.
__global__ void assign_kernel(const int* __restrict__ perm) {
    int k = blockIdx.x * blockDim.x + threadIdx.x;
    if (k >= Kneg) return;
    int p = perm[k];
#pragma unroll
    for (int t = 0; t < 2; t++) {
        int x = p + t;
        if (atomicExch(&g_mark[x], 1) == 0) {
            int s = atomicAdd(&g_Ucnt, 1);
            g_slot[x] = s;
            g_Ulist[s] = x;
        }
    }
}

// ================= 1. norms + positive logit =================
__global__ void norms_kernel(const float* __restrict__ zi, const float* __restrict__ zj) {
    int warp = (blockIdx.x * blockDim.x + threadIdx.x) >> 5;
    int lane = threadIdx.x & 31;
    if (warp >= Bsz) return;
    const float4* a = (const float4*)(zi + (size_t)warp * Ddim);
    const float4* b = (const float4*)(zj + (size_t)warp * Ddim);
    float si = 0.f, sj = 0.f, dij = 0.f;
#pragma unroll
    for (int c = 0; c < 4; c++) {
        float4 x = a[c * 32 + lane];
        float4 y = b[c * 32 + lane];
        si  += x.x*x.x + x.y*x.y + x.z*x.z + x.w*x.w;
        sj  += y.x*y.x + y.y*y.y + y.z*y.z + y.w*y.w;
        dij += x.x*y.x + x.y*y.y + x.z*y.z + x.w*y.w;
    }
#pragma unroll
    for (int o = 16; o > 0; o >>= 1) {
        si  += __shfl_down_sync(0xffffffffu, si, o);
        sj  += __shfl_down_sync(0xffffffffu, sj, o);
        dij += __shfl_down_sync(0xffffffffu, dij, o);
    }
    if (lane == 0) {
        float ni = sqrtf(si), nj = sqrtf(sj);
        g_ni[warp] = ni;
        g_nj[warp] = nj;
        g_plog[warp] = dij / fmaxf(ni * nj, EPSN) * 2.0f;
    }
}

// ================= 2. fused: split_zi + split_zj + maps =================
__device__ __forceinline__ void split8(const float* __restrict__ src,
                                       __nv_bfloat16* __restrict__ hi_out,
                                       __nv_bfloat16* __restrict__ lo_out) {
    float4 a = *(const float4*)(src);
    float4 b = *(const float4*)(src + 4);
    __nv_bfloat16 h[8], l[8];
    float v[8] = {a.x, a.y, a.z, a.w, b.x, b.y, b.z, b.w};
#pragma unroll
    for (int q = 0; q < 8; q++) {
        h[q] = __float2bfloat16(v[q]);
        l[q] = __float2bfloat16(v[q] - __bfloat162float(h[q]));
    }
    *(uint4*)hi_out = *(uint4*)h;
    *(uint4*)lo_out = *(uint4*)l;
}

#define ZI_BLOCKS  2048
#define ZJ_BLOCKS  1024
#define MAP_BLOCKS 8

__global__ void prep_kernel(const float* __restrict__ zi, const float* __restrict__ zj,
                            const int* __restrict__ perm) {
    int blk = blockIdx.x;
    int tid = threadIdx.x;
    if (blk < ZI_BLOCKS) {
        int idx = blk * 256 + tid;                 // Bsz*64
        size_t off = (size_t)idx * 8;
        split8(zi + off, g_Ahi + off, g_Alo + off);
    } else if (blk < ZI_BLOCKS + ZJ_BLOCKS) {
        int idx = (blk - ZI_BLOCKS) * 256 + tid;   // NPAD*64
        int u = idx >> 6;
        int g = idx & 63;
        int row = g_Ulist[u];
        size_t doff = (size_t)u * Ddim + g * 8;
        size_t soff = (size_t)row * Ddim + g * 8;
        split8(zj + soff, g_Bhi + doff, g_Blo + doff);
    } else {
        int k = (blk - ZI_BLOCKS - ZJ_BLOCKS) * 256 + tid;
        if (k < Kneg) {
            int p = perm[k];
            g_map0[k] = g_slot[p];
            g_map1[k] = g_slot[p + 1];
            g_nj0[k] = g_nj[p];
            g_nj1[k] = g_nj[p + 1];
        }
    }
}

// ================= 3. GEMM: bf16 m16n8k16, 3-term, 3-stage swizzled pipeline =================
#define ARRB  8192                  // 128 rows x 64B
#define STGB  (4 * ARRB)            // 32768 B
#define NSTG  3
#define SMEM_TOTAL (NSTG * STGB)    // 98304 B
#define NCHUNK (Ddim / 32)          // 16

// phys 16B-chunk: c ^ ((row>>1)&3)  -- conflict-free for ldmatrix reads and cp.async stores
__global__ __launch_bounds__(256, 2) void gemm_bf16_kernel() {
    const int n0 = blockIdx.x * 128;
    const int m0 = blockIdx.y * 128;
    if (n0 >= g_Ucnt) return;

    extern __shared__ char sm[];
    const uint32_t sb = smem_u32(sm);

    const int tid  = threadIdx.x;
    const int lane = tid & 31;
    const int wid  = tid >> 5;
    const int wm   = wid >> 1;        // 0..3
    const int wn   = wid & 1;         // 0..1

    // ---- cp.async assignment: arr = tid>>6; 8 x 16B per thread per stage-fill ----
    const int arr = tid >> 6;         // 0:Ahi 1:Alo 2:Bhi 3:Blo
    const int lt  = tid & 63;
    const __nv_bfloat16* garr =
        (arr == 0) ? g_Ahi + (size_t)m0 * Ddim :
        (arr == 1) ? g_Alo + (size_t)m0 * Ddim :
        (arr == 2) ? g_Bhi + (size_t)n0 * Ddim :
                     g_Blo + (size_t)n0 * Ddim;

    // precompute per-thread store (row, phys) pairs
    uint32_t st_dst[8];
    uint32_t st_src[8];
#pragma unroll
    for (int q = 0; q < 8; q++) {
        int row = lt + 64 * (q >> 2);
        int c   = q & 3;
        int phys = c ^ ((row >> 1) & 3);
        st_dst[q] = (uint32_t)(arr * ARRB + row * 64 + phys * 16);
        st_src[q] = (uint32_t)(row * Ddim + c * 8);     // element offset
    }

    // precompute per-lane ldmatrix offsets (g=0; g=1 is ^32)
    uint32_t aoff[2];
#pragma unroll
    for (int mt = 0; mt < 2; mt++) {
        int row = wm * 32 + mt * 16 + (lane & 15);
        int ch  = (lane >> 4);                     // 0/1
        int phys = ch ^ ((row >> 1) & 3);
        aoff[mt] = (uint32_t)(row * 64 + phys * 16);
    }
    uint32_t boff[4];
#pragma unroll
    for (int p = 0; p < 4; p++) {
        int row = wn * 64 + p * 16 + (((lane >> 4) & 1) << 3) + (lane & 7);
        int ch  = (lane >> 3) & 1;
        int phys = ch ^ ((row >> 1) & 3);
        boff[p] = (uint32_t)(2 * ARRB + row * 64 + phys * 16);
    }

    float d[2][8][4];
#pragma unroll
    for (int mt = 0; mt < 2; mt++)
#pragma unroll
        for (int nt = 0; nt < 8; nt++)
#pragma unroll
            for (int q = 0; q < 4; q++) d[mt][nt][q] = 0.f;

    // prologue: chunks 0 and 1
#pragma unroll
    for (int ck = 0; ck < 2; ck++) {
        uint32_t stg = sb + ck * STGB;
#pragma unroll
        for (int q = 0; q < 8; q++)
            cp16(stg + st_dst[q], garr + ck * 32 + st_src[q]);
        cp_commit();
    }

    for (int c = 0; c < NCHUNK; c++) {
        if (c + 1 < NCHUNK) cp_wait1(); else cp_wait0();
        __syncthreads();

        // issue chunk c+2 into stage (c+2)%3 (safe: all warps past compute c-1)
        if (c + 2 < NCHUNK) {
            uint32_t stg = sb + ((c + 2) % NSTG) * STGB;
            const __nv_bfloat16* gsrc = garr + (c + 2) * 32;
#pragma unroll
            for (int q = 0; q < 8; q++)
                cp16(stg + st_dst[q], gsrc + st_src[q]);
            cp_commit();
        }

        const uint32_t s0 = sb + (c % NSTG) * STGB;
#pragma unroll
        for (int g = 0; g < 2; g++) {
            const uint32_t gx = (uint32_t)(g * 32);   // phys chunk xor trick: +k16 == ^32
            uint32_t ah[2][4], al[2][4];
#pragma unroll
            for (int mt = 0; mt < 2; mt++) {
                uint32_t ra = s0 + (aoff[mt] ^ gx);
                ldsm_x4(ra,        ah[mt][0], ah[mt][1], ah[mt][2], ah[mt][3]);
                ldsm_x4(ra + ARRB, al[mt][0], al[mt][1], al[mt][2], al[mt][3]);
            }
#pragma unroll
            for (int p = 0; p < 4; p++) {
                uint32_t bh[4], bl[4];
                uint32_t rb = s0 + (boff[p] ^ gx);
                ldsm_x4(rb,        bh[0], bh[1], bh[2], bh[3]);
                ldsm_x4(rb + ARRB, bl[0], bl[1], bl[2], bl[3]);
#pragma unroll
                for (int mt = 0; mt < 2; mt++) {
#pragma unroll
                    for (int j = 0; j < 2; j++) {
                        float* acc = d[mt][p * 2 + j];
                        mma_bf16(acc, ah[mt], bh + j * 2);
                        mma_bf16(acc, ah[mt], bl + j * 2);
                        mma_bf16(acc, al[mt], bh + j * 2);
                    }
                }
            }
        }
    }

    // ---- epilogue ----
#pragma unroll
    for (int mt = 0; mt < 2; mt++) {
        int r0 = m0 + wm * 32 + mt * 16 + (lane >> 2);
#pragma unroll
        for (int nt = 0; nt < 8; nt++) {
            int col = n0 + wn * 64 + nt * 8 + (lane & 3) * 2;
            float* p0 = g_C + (size_t)r0 * NPAD + col;
            float* p1 = g_C + (size_t)(r0 + 8) * NPAD + col;
            *(float2*)p0 = make_float2(d[mt][nt][0], d[mt][nt][1]);
            *(float2*)p1 = make_float2(d[mt][nt][2], d[mt][nt][3]);
        }
    }
}

// ================= 4. per-row logsumexp + rank counts =================
__global__ __launch_bounds__(256) void reduce_kernel(const int* __restrict__ perm) {
    __shared__ int   s_p[Kneg];
    __shared__ int   s_m0[Kneg];
    __shared__ int   s_m1[Kneg];
    __shared__ float s_n0[Kneg];
    __shared__ float s_n1[Kneg];
    __shared__ float redf[256];
    __shared__ int   redi[256];

    int tid = threadIdx.x;
    for (int k = tid; k < Kneg; k += 256) {
        s_p[k]  = perm[k];
        s_m0[k] = g_map0[k];
        s_m1[k] = g_map1[k];
        s_n0[k] = g_nj0[k];
        s_n1[k] = g_nj1[k];
    }
    __syncthreads();

    for (int r = 0; r < 8; r++) {
        int i = blockIdx.x * 8 + r;
        float ni = g_ni[i];
        float lp = g_plog[i];
        const float* Crow = g_C + (size_t)i * NPAD;

        float tmax = lp;
        for (int k = tid; k < Kneg; k += 256) {
            bool sel = (s_p[k] >= i);
            int slot  = sel ? s_m1[k] : s_m0[k];
            float njc = sel ? s_n1[k] : s_n0[k];
            float l = Crow[slot] / fmaxf(ni * njc, EPSN) * 2.0f;
            tmax = fmaxf(tmax, l);
        }
        redf[tid] = tmax;
        __syncthreads();
        for (int o = 128; o > 0; o >>= 1) {
            if (tid < o) redf[tid] = fmaxf(redf[tid], redf[tid + o]);
            __syncthreads();
        }
        float M = redf[0];
        __syncthreads();

        float s = 0.f;
        int cnt = 0;
        for (int k = tid; k < Kneg; k += 256) {
            bool sel = (s_p[k] >= i);
            int slot  = sel ? s_m1[k] : s_m0[k];
            float njc = sel ? s_n1[k] : s_n0[k];
            float l = Crow[slot] / fmaxf(ni * njc, EPSN) * 2.0f;
            s += expf(l - M);
            cnt += (l > lp) ? 1 : 0;
        }
        redf[tid] = s;
        redi[tid] = cnt;
        __syncthreads();
        for (int o = 128; o > 0; o >>= 1) {
            if (tid < o) { redf[tid] += redf[tid + o]; redi[tid] += redi[tid + o]; }
            __syncthreads();
        }
        if (tid == 0) {
            g_loss[i] = M + logf(redf[0] + expf(lp - M)) - lp;
            g_cnt[i]  = redi[0];
        }
        __syncthreads();
    }
}

// ================= 5. final reduction + state cleanup =================
__global__ void final_kernel(float* __restrict__ out) {
    __shared__ float sf[1024];
    __shared__ int   s1[1024];
    __shared__ int   s5[1024];
    int tid = threadIdx.x;
    float s = 0.f;
    int c1 = 0, c5 = 0;
    for (int i = tid; i < Bsz; i += 1024) {
        s += g_loss[i];
        int c = g_cnt[i];
        c1 += (c == 0) ? 1 : 0;
        c5 += (c <= 4) ? 1 : 0;
    }
    sf[tid] = s; s1[tid] = c1; s5[tid] = c5;
    __syncthreads();
    for (int o = 512; o > 0; o >>= 1) {
        if (tid < o) { sf[tid] += sf[tid + o]; s1[tid] += s1[tid + o]; s5[tid] += s5[tid + o]; }
        __syncthreads();
    }
    if (tid == 0) {
        out[0] = sf[0] / (float)Bsz;
        out[1] = 100.0f * (float)s1[0] / (float)Bsz;
        out[2] = 100.0f * (float)s5[0] / (float)Bsz;
        g_Ucnt = 0;                               // self-clean for next replay
    }
    for (int i = tid; i < Bsz; i += 1024) g_mark[i] = 0;
}

// ================= launch =================
extern "C" void kernel_launch(void* const* d_in, const int* in_sizes, int n_in,
                              void* d_out, int out_size) {
    const float* zi   = (const float*)d_in[0];
    const float* zj   = (const float*)d_in[1];
    const int*   perm = (const int*)d_in[2];
    float* out = (float*)d_out;

    cudaFuncSetAttribute(gemm_bf16_kernel, cudaFuncAttributeMaxDynamicSharedMemorySize, SMEM_TOTAL);

    assign_kernel<<<2, 1024>>>(perm);                                // 0
    norms_kernel<<<Bsz / 8, 256>>>(zi, zj);                          // 1
    prep_kernel<<<ZI_BLOCKS + ZJ_BLOCKS + MAP_BLOCKS, 256>>>(zi, zj, perm); // 2
    dim3 g(NPAD / 128, Bsz / 128);                                   // 32 x 64
    gemm_bf16_kernel<<<g, 256, SMEM_TOTAL>>>();                      // 3  (ncu target)
    reduce_kernel<<<Bsz / 8, 256>>>(perm);                           // 4
    final_kernel<<<1, 1024>>>(out);                                  // 5
}